// round 14
// baseline (speedup 1.0000x reference)
#include <cuda_runtime.h>
#include <math.h>
#include <stdint.h>

#define TLEN   1024
#define BATCH  4
#define EMBED  1024
#define NH     16
#define HD     64
#define QSCALE 0.125f
#define MROWS  (TLEN * BATCH)   // 4096

// Scratch (static device globals — no cudaMalloc anywhere)
__device__ float g_Q[BATCH * NH * TLEN * HD];                 // [b,h,t,d], pre-scaled
__device__ float g_K[BATCH * NH * TLEN * HD];
__device__ float g_V[BATCH * NH * TLEN * HD];
__device__ float g_P[(size_t)BATCH * NH * TLEN * TLEN];       // unnormalized exp tiles
__device__ float g_C[BATCH * NH * TLEN * 16];                 // per-(row,tile) corrections
__device__ float g_A[MROWS * EMBED];                          // attention context [t,b,e]

__device__ __forceinline__ uint32_t f2tf(float f) {
    uint32_t u;
    asm("cvt.rna.tf32.f32 %0, %1;" : "=r"(u) : "f"(f));
    return u;
}

__device__ __forceinline__ void mma_tf32(float* d, const uint32_t* a, const uint32_t* b) {
    asm volatile(
        "mma.sync.aligned.m16n8k8.row.col.f32.tf32.tf32.f32 "
        "{%0,%1,%2,%3}, {%4,%5,%6,%7}, {%8,%9}, {%0,%1,%2,%3};"
        : "+f"(d[0]), "+f"(d[1]), "+f"(d[2]), "+f"(d[3])
        : "r"(a[0]), "r"(a[1]), "r"(a[2]), "r"(a[3]), "r"(b[0]), "r"(b[1]));
}

// ---------------------------------------------------------------------------
// TF32 tensor-core GEMM (EXACT R8/R13 version — proven)
// ---------------------------------------------------------------------------
#define GEMM_SMEM_WORDS (4 * 128 * 36)
#define AS(buf, r, c) As[(buf) * 4608 + (r) * 36 + (c)]
#define BS(buf, r, c) Bs[(buf) * 4608 + (r) * 36 + (c)]

template <int EPI>
__global__ __launch_bounds__(256) void k_gemm_tf32(const float* __restrict__ Ain,
                                                   const float* __restrict__ B,
                                                   const float* __restrict__ bias,
                                                   float* __restrict__ C,
                                                   int K) {
    const float* A = (EPI == 0) ? Ain : (const float*)g_A;
    extern __shared__ uint32_t smraw[];
    uint32_t* As = smraw;
    uint32_t* Bs = smraw + 2 * 4608;
    const int tid  = threadIdx.x;
    const int lane = tid & 31;
    const int wid  = tid >> 5;
    const int wm   = (wid & 1) << 6;
    const int wn   = (wid >> 1) << 5;
    const int m0   = blockIdx.y << 7;
    const int n0   = blockIdx.x << 7;
    const int ldr = tid >> 3;
    const int ldc = (tid & 7) << 2;
    const int g4 = lane >> 2;
    const int g1 = lane & 3;

    float acc[4][4][4] = {};
    float4 av[4], bv[4];

    const float* Abase = A + (size_t)(m0 + ldr) * K + ldc;
    const float* Bbase = B + (size_t)(n0 + ldr) * K + ldc;

    #pragma unroll
    for (int r = 0; r < 4; r++) {
        av[r] = *(const float4*)(Abase + (size_t)(r << 5) * K);
        bv[r] = *(const float4*)(Bbase + (size_t)(r << 5) * K);
    }
    #pragma unroll
    for (int r = 0; r < 4; r++) {
        uint32_t* pa = &AS(0, (r << 5) + ldr, ldc);
        uint32_t* pb = &BS(0, (r << 5) + ldr, ldc);
        pa[0] = f2tf(av[r].x); pa[1] = f2tf(av[r].y); pa[2] = f2tf(av[r].z); pa[3] = f2tf(av[r].w);
        pb[0] = f2tf(bv[r].x); pb[1] = f2tf(bv[r].y); pb[2] = f2tf(bv[r].z); pb[3] = f2tf(bv[r].w);
    }
    __syncthreads();

    int cur = 0;
    for (int k0 = 0; k0 < K; k0 += 32) {
        const bool has_next = (k0 + 32 < K);
        if (has_next) {
            #pragma unroll
            for (int r = 0; r < 4; r++) {
                av[r] = *(const float4*)(Abase + (size_t)(r << 5) * K + k0 + 32);
                bv[r] = *(const float4*)(Bbase + (size_t)(r << 5) * K + k0 + 32);
            }
        }
        #pragma unroll
        for (int kk = 0; kk < 32; kk += 8) {
            uint32_t a[4][4], b[4][2];
            #pragma unroll
            for (int im = 0; im < 4; im++) {
                int mr = wm + (im << 4) + g4;
                a[im][0] = AS(cur, mr    , kk + g1    );
                a[im][1] = AS(cur, mr + 8, kk + g1    );
                a[im][2] = AS(cur, mr    , kk + g1 + 4);
                a[im][3] = AS(cur, mr + 8, kk + g1 + 4);
            }
            #pragma unroll
            for (int jn = 0; jn < 4; jn++) {
                int nr = wn + (jn << 3) + g4;
                b[jn][0] = BS(cur, nr, kk + g1    );
                b[jn][1] = BS(cur, nr, kk + g1 + 4);
            }
            #pragma unroll
            for (int im = 0; im < 4; im++)
                #pragma unroll
                for (int jn = 0; jn < 4; jn++)
                    mma_tf32(acc[im][jn], a[im], b[jn]);
        }
        if (has_next) {
            int nxt = cur ^ 1;
            #pragma unroll
            for (int r = 0; r < 4; r++) {
                uint32_t* pa = &AS(nxt, (r << 5) + ldr, ldc);
                uint32_t* pb = &BS(nxt, (r << 5) + ldr, ldc);
                pa[0] = f2tf(av[r].x); pa[1] = f2tf(av[r].y); pa[2] = f2tf(av[r].z); pa[3] = f2tf(av[r].w);
                pb[0] = f2tf(bv[r].x); pb[1] = f2tf(bv[r].y); pb[2] = f2tf(bv[r].z); pb[3] = f2tf(bv[r].w);
            }
            __syncthreads();
        }
        cur ^= 1;
    }

    #pragma unroll
    for (int im = 0; im < 4; im++)
        #pragma unroll
        for (int jn = 0; jn < 4; jn++)
            #pragma unroll
            for (int e = 0; e < 4; e++) {
                int m = m0 + wm + (im << 4) + g4 + ((e >> 1) << 3);
                int n = n0 + wn + (jn << 3) + (g1 << 1) + (e & 1);
                float v = acc[im][jn][e] + bias[n];
                if (EPI == 0) {
                    int t = m >> 2, bb = m & 3;
                    int c = n >> 10;
                    int ee = n & 1023;
                    int h = ee >> 6, d = ee & 63;
                    int idx = (((bb << 4) + h) * TLEN + t) * HD + d;
                    if (c == 0)      g_Q[idx] = v * QSCALE;
                    else if (c == 1) g_K[idx] = v;
                    else             g_V[idx] = v;
                } else {
                    C[(size_t)m * EMBED + n] = v;
                }
            }
}

// ---------------------------------------------------------------------------
// Fused flash attention, warp-per-16-rows (R13) + REGISTER-PIPELINED K/V/pad:
// LDGs for tile it+1 issue right after the publish barrier of tile it, hiding
// L2 latency under S-MMA + softmax + PV-MMA. Arithmetic identical to R13.
// ---------------------------------------------------------------------------
#define ATT_OFF_Q   0
#define ATT_OFF_K   8704
#define ATT_OFF_V   13056
#define ATT_OFF_MT  17408
#define ATT_OFF_PAD 19456
#define ATT_SMEM_WORDS 19520

__global__ __launch_bounds__(256) void k_attn(const int* __restrict__ pad) {
    extern __shared__ uint32_t sm[];
    uint32_t* Qs = sm + ATT_OFF_Q;
    uint32_t* Ks = sm + ATT_OFF_K;
    uint32_t* Vs = sm + ATT_OFF_V;
    float* mtl  = (float*)(sm + ATT_OFF_MT);
    int*   pads = (int*)(sm + ATT_OFF_PAD);

    const int bh = blockIdx.y;
    const int t0 = (7 - blockIdx.x) << 7;      // big tiles first
    const int b  = bh >> 4;
    const int h  = bh & 15;
    const int tid  = threadIdx.x;
    const int lane = tid & 31;
    const int wid  = tid >> 5;
    const int wm = wid << 4;                   // warp's 16-row block
    const int g4 = lane >> 2;
    const int g1 = lane & 3;

    const float* Qg = g_Q + (size_t)bh * TLEN * HD;
    const float* Kg = g_K + (size_t)bh * TLEN * HD;
    const float* Vg = g_V + (size_t)bh * TLEN * HD;
    float* Pg = g_P + (size_t)bh * TLEN * TLEN;

    // Q tile 128x64 -> smem (tf32)
    {
        int qr = tid >> 1;
        int qc = (tid & 1) << 5;
        #pragma unroll
        for (int j = 0; j < 8; j++) {
            float4 q = *(const float4*)(Qg + (size_t)(t0 + qr) * HD + qc + j * 4);
            uint32_t* p = &Qs[qr * 68 + qc + j * 4];
            p[0] = f2tf(q.x); p[1] = f2tf(q.y); p[2] = f2tf(q.z); p[3] = f2tf(q.w);
        }
    }

    const int row0 = wm + g4;
    const int row1 = wm + g4 + 8;
    float m_run0 = -1e30f, m_run1 = -1e30f;
    float l_run0 = 0.f, l_run1 = 0.f;
    float acc_o[8][4] = {};
    __syncthreads();

    const int nt = (t0 + 128) >> 6;
    const int kr = tid >> 2;                               // s row 0..63
    const int kc = (tid & 3) << 4;                         // d col base
    const int krp = (kr & 56) | ((kr & 7) >> 1) | ((kr & 1) << 2);  // permuted s col

    // Prologue: load tile 0 into registers
    float4 kf[4], vf[4];
    int padv;
    #pragma unroll
    for (int j = 0; j < 4; j++) {
        kf[j] = *(const float4*)(Kg + (size_t)kr * HD + kc + j * 4);
        vf[j] = *(const float4*)(Vg + (size_t)kr * HD + kc + j * 4);
    }
    padv = (tid < 64) ? pad[b * TLEN + tid] : 0;

    for (int it = 0; it < nt; it++) {
        const int s0 = it << 6;
        __syncthreads();                       // prev tile's Ks/Vs consumed
        #pragma unroll
        for (int j = 0; j < 4; j++) {
            uint32_t* p = &Ks[kr * 68 + kc + j * 4];
            p[0] = f2tf(kf[j].x); p[1] = f2tf(kf[j].y); p[2] = f2tf(kf[j].z); p[3] = f2tf(kf[j].w);
            Vs[(kc + j * 4 + 0) * 68 + krp] = f2tf(vf[j].x);
            Vs[(kc + j * 4 + 1) * 68 + krp] = f2tf(vf[j].y);
            Vs[(kc + j * 4 + 2) * 68 + krp] = f2tf(vf[j].z);
            Vs[(kc + j * 4 + 3) * 68 + krp] = f2tf(vf[j].w);
        }
        if (tid < 64) pads[tid] = padv;
        __syncthreads();

        // Prefetch tile it+1 (hidden under the MMAs below)
        if (it + 1 < nt) {
            const int sn = (it + 1) << 6;
            #pragma unroll
            for (int j = 0; j < 4; j++) {
                kf[j] = *(const float4*)(Kg + (size_t)(sn + kr) * HD + kc + j * 4);
                vf[j] = *(const float4*)(Vg + (size_t)(sn + kr) * HD + kc + j * 4);
            }
            padv = (tid < 64) ? pad[b * TLEN + sn + tid] : 0;
        }

        // ---- S = Q K^T : 16 rows x 64 cols per warp ----
        float accs[8][4] = {};
        #pragma unroll
        for (int kk = 0; kk < 64; kk += 8) {
            uint32_t a[4];
            a[0] = Qs[row0 * 68 + kk + g1];
            a[1] = Qs[row1 * 68 + kk + g1];
            a[2] = Qs[row0 * 68 + kk + g1 + 4];
            a[3] = Qs[row1 * 68 + kk + g1 + 4];
            #pragma unroll
            for (int jn = 0; jn < 8; jn++) {
                uint32_t bf[2];
                int nr = (jn << 3) + g4;
                bf[0] = Ks[nr * 68 + kk + g1];
                bf[1] = Ks[nr * 68 + kk + g1 + 4];
                mma_tf32(accs[jn], a, bf);
            }
        }

        // ---- mask + warp-local row max ----
        const int tg0 = t0 + row0;
        const int tg1 = t0 + row1;
        float m0 = -1e30f, m1 = -1e30f;
        #pragma unroll
        for (int jn = 0; jn < 8; jn++) {
            #pragma unroll
            for (int c = 0; c < 2; c++) {
                int s = s0 + (jn << 3) + (g1 << 1) + c;
                int pv = pads[s - s0];
                bool ok0 = (s <= tg0) && (pv == 0);
                bool ok1 = (s <= tg1) && (pv == 0);
                float v0 = ok0 ? accs[jn][c]     : -1e30f;
                float v1 = ok1 ? accs[jn][2 + c] : -1e30f;
                accs[jn][c]     = v0;
                accs[jn][2 + c] = v1;
                m0 = fmaxf(m0, v0);
                m1 = fmaxf(m1, v1);
            }
        }
        m0 = fmaxf(m0, __shfl_xor_sync(0xffffffffu, m0, 1));
        m0 = fmaxf(m0, __shfl_xor_sync(0xffffffffu, m0, 2));
        m1 = fmaxf(m1, __shfl_xor_sync(0xffffffffu, m1, 1));
        m1 = fmaxf(m1, __shfl_xor_sync(0xffffffffu, m1, 2));

        // ---- online update ----
        float mn0 = fmaxf(m_run0, m0);
        float mn1 = fmaxf(m_run1, m1);
        float f0 = __expf(m_run0 - mn0);
        float f1 = __expf(m_run1 - mn1);
        m_run0 = mn0; m_run1 = mn1;
        l_run0 *= f0;  l_run1 *= f1;
        #pragma unroll
        for (int dn = 0; dn < 8; dn++) {
            acc_o[dn][0] *= f0; acc_o[dn][1] *= f0;
            acc_o[dn][2] *= f1; acc_o[dn][3] *= f1;
        }
        if (g1 == 0) {
            mtl[row0 * 16 + it] = mn0;
            mtl[row1 * 16 + it] = mn1;
        }

        // ---- exp, gmem P write, row sums, build A-fragments ----
        uint32_t pa[8][4];
        float sum0 = 0.f, sum1 = 0.f;
        #pragma unroll
        for (int jn = 0; jn < 8; jn++) {
            int cb = s0 + (jn << 3) + (g1 << 1);
            float p00 = __expf(accs[jn][0] - mn0);
            float p01 = __expf(accs[jn][1] - mn0);
            float p10 = __expf(accs[jn][2] - mn1);
            float p11 = __expf(accs[jn][3] - mn1);
            sum0 += p00 + p01;
            sum1 += p10 + p11;
            *(float2*)(Pg + (size_t)tg0 * TLEN + cb) = make_float2(p00, p01);
            *(float2*)(Pg + (size_t)tg1 * TLEN + cb) = make_float2(p10, p11);
            pa[jn][0] = f2tf(p00);
            pa[jn][1] = f2tf(p10);
            pa[jn][2] = f2tf(p01);
            pa[jn][3] = f2tf(p11);
        }
        sum0 += __shfl_xor_sync(0xffffffffu, sum0, 1);
        sum0 += __shfl_xor_sync(0xffffffffu, sum0, 2);
        sum1 += __shfl_xor_sync(0xffffffffu, sum1, 1);
        sum1 += __shfl_xor_sync(0xffffffffu, sum1, 2);
        l_run0 += sum0;
        l_run1 += sum1;

        // ---- O += P~ V : P from registers, V permuted in smem ----
        #pragma unroll
        for (int ks = 0; ks < 8; ks++) {
            #pragma unroll
            for (int dn = 0; dn < 8; dn++) {
                uint32_t bf[2];
                int nr = (dn << 3) + g4;
                bf[0] = Vs[nr * 68 + (ks << 3) + g1];
                bf[1] = Vs[nr * 68 + (ks << 3) + g1 + 4];
                mma_tf32(acc_o[dn], pa[ks], bf);
            }
        }
    }

    // ---- epilogue: O/l -> g_A; corrections -> g_C ----
    const int tg0 = t0 + row0;
    const int tg1 = t0 + row1;
    float inv0 = 1.f / l_run0;
    float inv1 = 1.f / l_run1;
    #pragma unroll
    for (int dn = 0; dn < 8; dn++) {
        int d = (dn << 3) + (g1 << 1);
        float* o0 = g_A + ((size_t)tg0 * BATCH + b) * EMBED + (h << 6) + d;
        float* o1 = g_A + ((size_t)tg1 * BATCH + b) * EMBED + (h << 6) + d;
        *(float2*)o0 = make_float2(acc_o[dn][0] * inv0, acc_o[dn][1] * inv0);
        *(float2*)o1 = make_float2(acc_o[dn][2] * inv1, acc_o[dn][3] * inv1);
    }
    if (g1 == 0) {
        for (int it2 = 0; it2 < nt; it2++) {
            g_C[((size_t)bh * TLEN + tg0) * 16 + it2] = __expf(mtl[row0 * 16 + it2] - m_run0) * inv0;
            g_C[((size_t)bh * TLEN + tg1) * 16 + it2] = __expf(mtl[row1 * 16 + it2] - m_run1) * inv1;
        }
    }
}

// ---------------------------------------------------------------------------
// avg_weights[b,t,s] = (1/16) sum_h P~[bh,t,s] * C[bh,t,s>>6]; 0 for s>t.
// ---------------------------------------------------------------------------
__global__ __launch_bounds__(256) void k_avg(float* __restrict__ outAvg) {
    const int idx = blockIdx.x * 256 + threadIdx.x;
    const int s = idx & 1023;
    const int t = (idx >> 10) & 1023;
    const int b = idx >> 20;
    if (s > t) { outAvg[idx] = 0.f; return; }
    const int tile = s >> 6;
    float sum = 0.f;
    #pragma unroll
    for (int h = 0; h < 16; h++) {
        size_t base = (size_t)((b << 4) + h) * TLEN + t;
        sum += g_P[base * TLEN + s] * g_C[base * 16 + tile];
    }
    outAvg[idx] = sum * 0.0625f;
}

// ---------------------------------------------------------------------------
extern "C" void kernel_launch(void* const* d_in, const int* in_sizes, int n_in,
                              void* d_out, int out_size) {
    const float* query = (const float*)d_in[0];
    const int*   mask  = (const int*)d_in[1];   // numpy bool widened to int32
    const float* w_in  = (const float*)d_in[2];
    const float* b_in  = (const float*)d_in[3];
    const float* w_out = (const float*)d_in[4];
    const float* b_out = (const float*)d_in[5];

    float* outAttn = (float*)d_out;                                   // [T,B,E]
    float* outAvg  = (float*)d_out + (size_t)MROWS * EMBED;           // [B,T,S]

    static cudaStream_t s_avg = nullptr;
    static cudaEvent_t ev_fork = nullptr, ev_join = nullptr;
    if (s_avg == nullptr) {
        cudaStreamCreateWithFlags(&s_avg, cudaStreamNonBlocking);
        cudaEventCreateWithFlags(&ev_fork, cudaEventDisableTiming);
        cudaEventCreateWithFlags(&ev_join, cudaEventDisableTiming);
    }

    const int gemm_smem = GEMM_SMEM_WORDS * 4;   // 73,728 B
    const int attn_smem = ATT_SMEM_WORDS * 4;    // 78,080 B
    cudaFuncSetAttribute(k_gemm_tf32<0>, cudaFuncAttributeMaxDynamicSharedMemorySize, gemm_smem);
    cudaFuncSetAttribute(k_gemm_tf32<1>, cudaFuncAttributeMaxDynamicSharedMemorySize, gemm_smem);
    cudaFuncSetAttribute(k_attn,         cudaFuncAttributeMaxDynamicSharedMemorySize, attn_smem);

    k_gemm_tf32<0><<<dim3(24, 32), 256, gemm_smem>>>(query, w_in, b_in, nullptr, EMBED);
    k_attn<<<dim3(8, 64), 256, attn_smem>>>(mask);

    // Fork: avg depends only on k_attn; run concurrently with out-proj.
    cudaEventRecord(ev_fork, 0);
    cudaStreamWaitEvent(s_avg, ev_fork, 0);
    k_avg<<<16384, 256, 0, s_avg>>>(outAvg);
    cudaEventRecord(ev_join, s_avg);

    k_gemm_tf32<1><<<dim3(8, 32), 256, gemm_smem>>>(nullptr, w_out, b_out, outAttn, EMBED);

    cudaStreamWaitEvent(0, ev_join, 0);
}